// round 9
// baseline (speedup 1.0000x reference)
#include <cuda_runtime.h>
#include <math.h>
#include <stdint.h>

#define BATCH    8
#define CH       128
#define T_AUDIO  16384
#define COND_CH  80
#define T_MEL    32
#define N_LAYERS 4
#define KPL      (CH*CH*3)        /* 49152 */
#define KC       (KPL*N_LAYERS)   /* 196608 */
#define BC       (CH*N_LAYERS)    /* 512 */

#define KSTEPS   24               /* 384/16 bf16 k-steps */
#define NT       128              /* t-tile */
#define TILES    (T_AUDIO/NT)     /* 128 */
#define CTAS_X   18
#define WFULL    24576            /* per (b,l): 192 frag-rows x 32 lanes x 4 words */
#define PAD      16
#define XROW     (T_AUDIO + 2*PAD)  /* 16416 words per packed pair-row */
#define XSTR     152              /* smem x stride: 152%32==24 -> B frags conflict-free */
#define XCHUNKS  36               /* 144 words = 36 x 16B per row */
#define PACK_BLKS 8192

// ---------------- device scratch ----------------
__device__ float    g_hmean[BATCH*64];
__device__ uint32_t g_Wh[BATCH*N_LAYERS*WFULL];
__device__ float    g_bias[BATCH*N_LAYERS*CH];
__device__ float    g_buf0[(size_t)BATCH*CH*T_AUDIO];
__device__ float    g_buf1[(size_t)BATCH*CH*T_AUDIO];
__device__ uint32_t g_xbf0[(size_t)BATCH*64*XROW];   // bf16x2 shadow (pads stay zero)
__device__ uint32_t g_xbf1[(size_t)BATCH*64*XROW];

__device__ __forceinline__ float gelu_exact(float x) {
    return 0.5f * x * (1.0f + erff(x * 0.7071067811865475f));
}
__device__ __forceinline__ uint32_t pack_bf16x2(float lo, float hi) {
    uint32_t u;
    asm("cvt.rn.bf16x2.f32 %0, %1, %2;" : "=r"(u) : "f"(hi), "f"(lo));
    return u;
}
__device__ __forceinline__ uint32_t smem_u32(const void* p) {
    uint32_t a;
    asm("{ .reg .u64 t; cvta.to.shared.u64 t, %1; cvt.u32.u64 %0, t; }" : "=r"(a) : "l"(p));
    return a;
}
__device__ __forceinline__ void cp16(uint32_t dst, const void* src) {
    asm volatile("cp.async.cg.shared.global [%0], [%1], 16;" :: "r"(dst), "l"(src));
}
#define CP_COMMIT() asm volatile("cp.async.commit_group;" ::: "memory")
#define CP_WAIT0()  asm volatile("cp.async.wait_group 0;" ::: "memory")

#define MMA16(d_, a_, b_) \
  asm volatile("mma.sync.aligned.m16n8k16.row.col.f32.bf16.bf16.f32 " \
    "{%0,%1,%2,%3}, {%4,%5,%6,%7}, {%8,%9}, {%0,%1,%2,%3};" \
    : "+f"((d_)[0]), "+f"((d_)[1]), "+f"((d_)[2]), "+f"((d_)[3]) \
    : "r"((a_)[0]), "r"((a_)[1]), "r"((a_)[2]), "r"((a_)[3]), \
      "r"((b_)[0]), "r"((b_)[1]))

// =========================================================================
// Kernel A: conditioning net (unchanged)
// =========================================================================
__global__ void condnet_kernel(const float* __restrict__ cond,
                               const float* __restrict__ w0, const float* __restrict__ b0,
                               const float* __restrict__ w1, const float* __restrict__ b1) {
    extern __shared__ float smemf[];
    float* sc  = smemf;
    float* sw0 = sc  + COND_CH*T_MEL;
    float* sw1 = sw0 + 64*COND_CH*5;
    float* sh0 = sw1 + 64*64*3;
    float* sh1 = sh0 + 64*T_MEL;

    const int b = blockIdx.x;
    const int tid = threadIdx.x;

    for (int i = tid; i < COND_CH*T_MEL; i += 256) sc[i]  = cond[b*COND_CH*T_MEL + i];
    for (int i = tid; i < 64*COND_CH*5;  i += 256) sw0[i] = w0[i];
    for (int i = tid; i < 64*64*3;       i += 256) sw1[i] = w1[i];
    __syncthreads();

    const int og = tid >> 5;
    const int t  = tid & 31;

    float acc[8];
    #pragma unroll
    for (int r = 0; r < 8; ++r) acc[r] = b0[og*8 + r];
    for (int i = 0; i < COND_CH; ++i) {
        #pragma unroll
        for (int k = 0; k < 5; ++k) {
            int tt = t + k - 2;
            if (tt >= 0 && tt < T_MEL) {
                float xv = sc[i*T_MEL + tt];
                #pragma unroll
                for (int r = 0; r < 8; ++r)
                    acc[r] += sw0[((og*8 + r)*COND_CH + i)*5 + k] * xv;
            }
        }
    }
    #pragma unroll
    for (int r = 0; r < 8; ++r) sh0[(og*8 + r)*T_MEL + t] = gelu_exact(acc[r]);
    __syncthreads();

    #pragma unroll
    for (int r = 0; r < 8; ++r) acc[r] = b1[og*8 + r];
    for (int i = 0; i < 64; ++i) {
        #pragma unroll
        for (int k = 0; k < 3; ++k) {
            int tt = t + k - 1;
            if (tt >= 0 && tt < T_MEL) {
                float xv = sh0[i*T_MEL + tt];
                #pragma unroll
                for (int r = 0; r < 8; ++r)
                    acc[r] += sw1[((og*8 + r)*64 + i)*3 + k] * xv;
            }
        }
    }
    #pragma unroll
    for (int r = 0; r < 8; ++r) sh1[(og*8 + r)*T_MEL + t] = gelu_exact(acc[r]);
    __syncthreads();

    if (tid < 64) {
        float s = 0.0f;
        #pragma unroll
        for (int tt = 0; tt < T_MEL; ++tt) s += sh1[tid*T_MEL + tt];
        g_hmean[b*64 + tid] = s * (1.0f/T_MEL);
    }
}

// =========================================================================
// Kernel B (prep): blocks 0..385 = LVC weights -> bf16x2 fragment-major
// (unified layout: frag row = ks*8 + co_block); blocks 386.. = pack x.
// =========================================================================
__global__ void prep_kernel(const float* __restrict__ w2,
                            const float* __restrict__ b2,
                            const float* __restrict__ x) {
    const int tid = threadIdx.x;

    if (blockIdx.x >= 386) {
        const int i = blockIdx.x - 386;          // < 8192
        const int tc = i & 15;
        const int p  = (i >> 4) & 63;
        const int b  = i >> 10;
        const int t  = (tc*256 + tid)*4;
        const float4 a = *(const float4*)&x[((size_t)(b*CH + 2*p))*T_AUDIO + t];
        const float4 c = *(const float4*)&x[((size_t)(b*CH + 2*p + 1))*T_AUDIO + t];
        uint4 o;
        o.x = pack_bf16x2(a.x, c.x);
        o.y = pack_bf16x2(a.y, c.y);
        o.z = pack_bf16x2(a.z, c.z);
        o.w = pack_bf16x2(a.w, c.w);
        *(uint4*)&g_xbf0[(size_t)(b*64 + p)*XROW + PAD + t] = o;
        return;
    }

    __shared__ float sh[BATCH*64];
    for (int i = tid; i < BATCH*64; i += 256) sh[i] = g_hmean[i];
    __syncthreads();

    if (blockIdx.x < 384) {
        const int gidx = blockIdx.x*256 + tid;     // < 98304
        const int l    = gidx / WFULL;
        const int e3   = gidx - l*WFULL;           // < 24576
        const int j    = e3 & 3;
        const int lane = (e3 >> 2) & 31;
        const int cb   = (e3 >> 7) & 7;            // co block (16 co)
        const int ks   = e3 >> 10;                 // 0..23
        const int co   = cb*16 + (lane >> 2) + (j & 1)*8;
        const int kl0  = (lane & 3)*2 + ((j >> 1) & 1)*8;
        const int kg0  = ks*16 + kl0;
        const int kk   = kg0 >> 7;
        const int ci0  = kg0 & 127;
        const size_t r0 = (size_t)l*KPL + (size_t)co*384 + ci0*3 + kk;
        const size_t r1 = r0 + 3;

        float a0[BATCH], a1[BATCH];
        #pragma unroll
        for (int b = 0; b < BATCH; ++b) { a0[b] = 0.0f; a1[b] = 0.0f; }
        const float4* wr0 = (const float4*)(w2 + r0*64);
        const float4* wr1 = (const float4*)(w2 + r1*64);
        #pragma unroll 4
        for (int q = 0; q < 16; ++q) {
            float4 u = wr0[q], v = wr1[q];
            #pragma unroll
            for (int b = 0; b < BATCH; ++b) {
                const float* h = sh + b*64 + q*4;
                a0[b] += u.x*h[0] + u.y*h[1] + u.z*h[2] + u.w*h[3];
                a1[b] += v.x*h[0] + v.y*h[1] + v.z*h[2] + v.w*h[3];
            }
        }
        const float bi0 = b2[r0], bi1 = b2[r1];
        #pragma unroll
        for (int b = 0; b < BATCH; ++b)
            g_Wh[(size_t)(b*N_LAYERS + l)*WFULL + e3] =
                pack_bf16x2(a0[b] + bi0, a1[b] + bi1);
    } else {
        const int idx = (blockIdx.x - 384)*256 + tid;   // < 512
        const size_t c = (size_t)KC + idx;
        float acc[BATCH];
        #pragma unroll
        for (int b = 0; b < BATCH; ++b) acc[b] = 0.0f;
        const float4* wr = (const float4*)(w2 + c*64);
        #pragma unroll 4
        for (int q = 0; q < 16; ++q) {
            float4 w = wr[q];
            #pragma unroll
            for (int b = 0; b < BATCH; ++b) {
                const float* h = sh + b*64 + q*4;
                acc[b] += w.x*h[0] + w.y*h[1] + w.z*h[2] + w.w*h[3];
            }
        }
        const float bias = b2[c];
        #pragma unroll
        for (int b = 0; b < BATCH; ++b)
            g_bias[b*N_LAYERS*CH + idx] = acc[b] + bias;
    }
}

// =========================================================================
// Conv via bf16 mma + cp.async double buffering. 256 threads, 8 warps,
// 1 CTA/SM. CTA = (b), 128co x 128t tiles, strided.
// Warp (wr=wid&1 -> 64co, wc=wid>>1 -> 32t): mt=4 x nt=4 -> 192 B/HMMA.
// =========================================================================
#define SMEM_CONV ((WFULL + 2*64*XSTR + 256) * 4)

template<int DIL, bool FINAL>
__global__ void __launch_bounds__(256, 1)
lvc_conv_bf16(const uint32_t* __restrict__ xbf_in, uint32_t* __restrict__ xbf_out,
              const float* __restrict__ xres, float* __restrict__ yout,
              int layer, const float* __restrict__ alpha) {
    extern __shared__ __align__(16) uint32_t smem[];
    uint32_t* sW  = smem;                       // WFULL
    uint32_t* sX[2] = { smem + WFULL, smem + WFULL + 64*XSTR };
    float*    sB  = (float*)(smem + WFULL + 2*64*XSTR);   // 128
    float*    sAl = sB + 128;                              // 128

    const int b    = blockIdx.y;
    const int tid  = threadIdx.x;
    const int wid  = tid >> 5;
    const int lane = tid & 31;
    const int wr   = wid & 1;                   // co group (64 co)
    const int wc   = wid >> 1;                  // t group (32 t)

    // stage W via cp.async
    {
        const uint32_t dW = smem_u32(sW);
        const uint32_t* Wg = g_Wh + (size_t)(b*N_LAYERS + layer)*WFULL;
        #pragma unroll
        for (int i = tid; i < WFULL/4; i += 256)
            cp16(dW + i*16, Wg + i*4);
    }
    if (tid < 128) sB[tid] = g_bias[(b*N_LAYERS + layer)*CH + tid];
    if (FINAL && tid >= 128 && tid < 256) sAl[tid - 128] = alpha[tid - 128];

    const uint32_t* xin_b = xbf_in + (size_t)b*64*XROW;
    const uint32_t dX[2] = { smem_u32(sX[0]), smem_u32(sX[1]) };

    // stage first tile
    int tile = blockIdx.x;
    {
        const int t0 = tile * NT;
        #pragma unroll
        for (int idx = tid; idx < 64*XCHUNKS; idx += 256) {
            const int row = idx / XCHUNKS;
            const int ch  = idx - row*XCHUNKS;
            cp16(dX[0] + (row*XSTR + ch*4)*4,
                 xin_b + (size_t)row*XROW + (PAD - 8 + t0) + ch*4);
        }
        CP_COMMIT();
    }

    const float* xr_b = xres + (size_t)b*CH*T_AUDIO;
    float*       yo_b = yout + (size_t)b*CH*T_AUDIO;
    uint32_t*    xo_b = FINAL ? nullptr : (xbf_out + (size_t)b*64*XROW);

    int bufi = 0;
    for (; tile < TILES; tile += CTAS_X) {
        const int t0 = tile * NT;
        CP_WAIT0();
        __syncthreads();

        const int nxt = tile + CTAS_X;
        if (nxt < TILES) {
            const int nt0 = nxt * NT;
            #pragma unroll
            for (int idx = tid; idx < 64*XCHUNKS; idx += 256) {
                const int row = idx / XCHUNKS;
                const int ch  = idx - row*XCHUNKS;
                cp16(dX[bufi^1] + (row*XSTR + ch*4)*4,
                     xin_b + (size_t)row*XROW + (PAD - 8 + nt0) + ch*4);
            }
            CP_COMMIT();
        }

        const uint32_t* sXb = sX[bufi];
        float acc[4][4][4];
        #pragma unroll
        for (int mt = 0; mt < 4; ++mt)
            #pragma unroll
            for (int n = 0; n < 4; ++n)
                #pragma unroll
                for (int q = 0; q < 4; ++q) acc[mt][n][q] = 0.0f;

        #pragma unroll 1
        for (int kk = 0; kk < 3; ++kk) {
            #pragma unroll
            for (int ks8 = 0; ks8 < 8; ++ks8) {
                const int ks   = kk*8 + ks8;
                const int row0 = ks8*8 + (lane & 3);
                const uint32_t* xrow = sXb + row0*XSTR + wc*32 + (lane >> 2)
                                       + 8 + (kk - 1)*DIL;
                uint32_t a[4][4];
                #pragma unroll
                for (int mt = 0; mt < 4; ++mt) {
                    const uint4 av = *(const uint4*)(sW + ((ks*8 + wr*4 + mt)*32 + lane)*4);
                    a[mt][0] = av.x; a[mt][1] = av.y; a[mt][2] = av.z; a[mt][3] = av.w;
                }
                #pragma unroll
                for (int n = 0; n < 4; ++n) {
                    uint32_t bf[2];
                    bf[0] = xrow[n*8];
                    bf[1] = xrow[n*8 + 4*XSTR];
                    MMA16(acc[0][n], a[0], bf);
                    MMA16(acc[1][n], a[1], bf);
                    MMA16(acc[2][n], a[2], bf);
                    MMA16(acc[3][n], a[3], bf);
                }
            }
        }

        // epilogue
        #pragma unroll
        for (int mt = 0; mt < 4; ++mt) {
            #pragma unroll
            for (int n = 0; n < 4; ++n) {
                const int c0 = wc*32 + n*8 + (lane & 3)*2;
                #pragma unroll
                for (int h = 0; h < 2; ++h) {
                    const int cog = wr*64 + mt*16 + (lane >> 2) + h*8;
                    const float bias = sB[cog];
                    const float2 xv = *(const float2*)&xr_b[(size_t)cog*T_AUDIO + t0 + c0];
                    float y0 = acc[mt][n][h*2+0] + bias + xv.x;
                    float y1 = acc[mt][n][h*2+1] + bias + xv.y;
                    if (FINAL) {
                        const float a = sAl[cog];
                        const float inva = 1.0f/(a + 1e-8f);
                        float s0 = sinf(a*y0), s1 = sinf(a*y1);
                        y0 += inva*s0*s0;
                        y1 += inva*s1*s1;
                    }
                    float2 v; v.x = y0; v.y = y1;
                    *(float2*)&yo_b[(size_t)cog*T_AUDIO + t0 + c0] = v;
                    if (!FINAL) {
                        const float o0 = __shfl_xor_sync(0xffffffffu, y0, 4);
                        const float o1 = __shfl_xor_sync(0xffffffffu, y1, 4);
                        if ((lane & 4) == 0) {
                            uint2 w;
                            w.x = pack_bf16x2(y0, o0);
                            w.y = pack_bf16x2(y1, o1);
                            const int prow = cog >> 1;
                            *(uint2*)&xo_b[(size_t)prow*XROW + PAD + t0 + c0] = w;
                        }
                    }
                }
            }
        }
        bufi ^= 1;
    }
}

// =========================================================================
extern "C" void kernel_launch(void* const* d_in, const int* in_sizes, int n_in,
                              void* d_out, int out_size) {
    const float* x     = (const float*)d_in[0];
    const float* cond  = (const float*)d_in[1];
    const float* w0    = (const float*)d_in[2];
    const float* b0    = (const float*)d_in[3];
    const float* w1    = (const float*)d_in[4];
    const float* b1    = (const float*)d_in[5];
    const float* w2    = (const float*)d_in[6];
    const float* b2    = (const float*)d_in[7];
    const float* alpha = (const float*)d_in[8];
    float* out = (float*)d_out;

    float *buf0, *buf1;
    uint32_t *xbf0, *xbf1;
    cudaGetSymbolAddress((void**)&buf0, g_buf0);
    cudaGetSymbolAddress((void**)&buf1, g_buf1);
    cudaGetSymbolAddress((void**)&xbf0, g_xbf0);
    cudaGetSymbolAddress((void**)&xbf1, g_xbf1);

    const int smemA = (COND_CH*T_MEL + 64*COND_CH*5 + 64*64*3 + 64*T_MEL + 64*T_MEL)
                      * (int)sizeof(float);
    cudaFuncSetAttribute(condnet_kernel, cudaFuncAttributeMaxDynamicSharedMemorySize, smemA);
    condnet_kernel<<<BATCH, 256, smemA>>>(cond, w0, b0, w1, b1);

    prep_kernel<<<386 + PACK_BLKS, 256>>>(w2, b2, x);

    cudaFuncSetAttribute(lvc_conv_bf16<1,false>, cudaFuncAttributeMaxDynamicSharedMemorySize, SMEM_CONV);
    cudaFuncSetAttribute(lvc_conv_bf16<2,false>, cudaFuncAttributeMaxDynamicSharedMemorySize, SMEM_CONV);
    cudaFuncSetAttribute(lvc_conv_bf16<4,false>, cudaFuncAttributeMaxDynamicSharedMemorySize, SMEM_CONV);
    cudaFuncSetAttribute(lvc_conv_bf16<8,true >, cudaFuncAttributeMaxDynamicSharedMemorySize, SMEM_CONV);

    dim3 grid(CTAS_X, BATCH);
    lvc_conv_bf16<1,false><<<grid, 256, SMEM_CONV>>>(xbf0, xbf1, x,    buf0, 0, nullptr);
    lvc_conv_bf16<2,false><<<grid, 256, SMEM_CONV>>>(xbf1, xbf0, buf0, buf1, 1, nullptr);
    lvc_conv_bf16<4,false><<<grid, 256, SMEM_CONV>>>(xbf0, xbf1, buf1, buf0, 2, nullptr);
    lvc_conv_bf16<8,true ><<<grid, 256, SMEM_CONV>>>(xbf1, nullptr, buf0, out, 3, alpha);
}

// round 10
// speedup vs baseline: 1.4721x; 1.4721x over previous
#include <cuda_runtime.h>
#include <math.h>
#include <stdint.h>

#define BATCH    8
#define CH       128
#define T_AUDIO  16384
#define COND_CH  80
#define T_MEL    32
#define N_LAYERS 4
#define KPL      (CH*CH*3)        /* 49152 */
#define KC       (KPL*N_LAYERS)   /* 196608 */
#define BC       (CH*N_LAYERS)    /* 512 */

#define NT       128              /* output chunk */
#define TILES    (T_AUDIO/NT)     /* 128 */
#define CTAS_X   18
#define WFULL    24576            /* per (b,l): 192 frag-rows x 32 lanes x 4 words */
#define BUFW     160              /* compute grid width (chunk + 2*16 halo) */
#define YSTR     168              /* yf32 stride: 168%32==8 -> conflict-free 64b phases */
#define XBW      184              /* xbf stride: 184%32==24 -> B frags conflict-free */

// ---------------- device scratch ----------------
__device__ float    g_hmean[BATCH*64];
__device__ uint32_t g_Wh[BATCH*N_LAYERS*WFULL];
__device__ float    g_bias[BATCH*N_LAYERS*CH];

__device__ __forceinline__ float gelu_exact(float x) {
    return 0.5f * x * (1.0f + erff(x * 0.7071067811865475f));
}
__device__ __forceinline__ uint32_t pack_bf16x2(float lo, float hi) {
    uint32_t u;
    asm("cvt.rn.bf16x2.f32 %0, %1, %2;" : "=r"(u) : "f"(hi), "f"(lo));
    return u;
}
__device__ __forceinline__ uint32_t smem_u32(const void* p) {
    uint32_t a;
    asm("{ .reg .u64 t; cvta.to.shared.u64 t, %1; cvt.u32.u64 %0, t; }" : "=r"(a) : "l"(p));
    return a;
}
__device__ __forceinline__ void cp16(uint32_t dst, const void* src) {
    asm volatile("cp.async.cg.shared.global [%0], [%1], 16;" :: "r"(dst), "l"(src));
}
#define CP_COMMIT() asm volatile("cp.async.commit_group;" ::: "memory")
#define CP_WAIT0()  asm volatile("cp.async.wait_group 0;" ::: "memory")

#define MMA16(d_, a_, b_) \
  asm volatile("mma.sync.aligned.m16n8k16.row.col.f32.bf16.bf16.f32 " \
    "{%0,%1,%2,%3}, {%4,%5,%6,%7}, {%8,%9}, {%0,%1,%2,%3};" \
    : "+f"((d_)[0]), "+f"((d_)[1]), "+f"((d_)[2]), "+f"((d_)[3]) \
    : "r"((a_)[0]), "r"((a_)[1]), "r"((a_)[2]), "r"((a_)[3]), \
      "r"((b_)[0]), "r"((b_)[1]))

// =========================================================================
// Kernel A: conditioning net (unchanged)
// =========================================================================
__global__ void condnet_kernel(const float* __restrict__ cond,
                               const float* __restrict__ w0, const float* __restrict__ b0,
                               const float* __restrict__ w1, const float* __restrict__ b1) {
    extern __shared__ float smemf[];
    float* sc  = smemf;
    float* sw0 = sc  + COND_CH*T_MEL;
    float* sw1 = sw0 + 64*COND_CH*5;
    float* sh0 = sw1 + 64*64*3;
    float* sh1 = sh0 + 64*T_MEL;

    const int b = blockIdx.x;
    const int tid = threadIdx.x;

    for (int i = tid; i < COND_CH*T_MEL; i += 256) sc[i]  = cond[b*COND_CH*T_MEL + i];
    for (int i = tid; i < 64*COND_CH*5;  i += 256) sw0[i] = w0[i];
    for (int i = tid; i < 64*64*3;       i += 256) sw1[i] = w1[i];
    __syncthreads();

    const int og = tid >> 5;
    const int t  = tid & 31;

    float acc[8];
    #pragma unroll
    for (int r = 0; r < 8; ++r) acc[r] = b0[og*8 + r];
    for (int i = 0; i < COND_CH; ++i) {
        #pragma unroll
        for (int k = 0; k < 5; ++k) {
            int tt = t + k - 2;
            if (tt >= 0 && tt < T_MEL) {
                float xv = sc[i*T_MEL + tt];
                #pragma unroll
                for (int r = 0; r < 8; ++r)
                    acc[r] += sw0[((og*8 + r)*COND_CH + i)*5 + k] * xv;
            }
        }
    }
    #pragma unroll
    for (int r = 0; r < 8; ++r) sh0[(og*8 + r)*T_MEL + t] = gelu_exact(acc[r]);
    __syncthreads();

    #pragma unroll
    for (int r = 0; r < 8; ++r) acc[r] = b1[og*8 + r];
    for (int i = 0; i < 64; ++i) {
        #pragma unroll
        for (int k = 0; k < 3; ++k) {
            int tt = t + k - 1;
            if (tt >= 0 && tt < T_MEL) {
                float xv = sh0[i*T_MEL + tt];
                #pragma unroll
                for (int r = 0; r < 8; ++r)
                    acc[r] += sw1[((og*8 + r)*64 + i)*3 + k] * xv;
            }
        }
    }
    #pragma unroll
    for (int r = 0; r < 8; ++r) sh1[(og*8 + r)*T_MEL + t] = gelu_exact(acc[r]);
    __syncthreads();

    if (tid < 64) {
        float s = 0.0f;
        #pragma unroll
        for (int tt = 0; tt < T_MEL; ++tt) s += sh1[tid*T_MEL + tt];
        g_hmean[b*64 + tid] = s * (1.0f/T_MEL);
    }
}

// =========================================================================
// Kernel B: LVC weights -> bf16x2 fragment-major (unified cb layout)
// =========================================================================
__global__ void weights_kernel(const float* __restrict__ w2,
                               const float* __restrict__ b2) {
    __shared__ float sh[BATCH*64];
    const int tid = threadIdx.x;
    for (int i = tid; i < BATCH*64; i += 256) sh[i] = g_hmean[i];
    __syncthreads();

    if (blockIdx.x < 384) {
        const int gidx = blockIdx.x*256 + tid;     // < 98304
        const int l    = gidx / WFULL;
        const int e3   = gidx - l*WFULL;
        const int j    = e3 & 3;
        const int lane = (e3 >> 2) & 31;
        const int cb   = (e3 >> 7) & 7;
        const int ks   = e3 >> 10;
        const int co   = cb*16 + (lane >> 2) + (j & 1)*8;
        const int kl0  = (lane & 3)*2 + ((j >> 1) & 1)*8;
        const int kg0  = ks*16 + kl0;
        const int kk   = kg0 >> 7;
        const int ci0  = kg0 & 127;
        const size_t r0 = (size_t)l*KPL + (size_t)co*384 + ci0*3 + kk;
        const size_t r1 = r0 + 3;

        float a0[BATCH], a1[BATCH];
        #pragma unroll
        for (int b = 0; b < BATCH; ++b) { a0[b] = 0.0f; a1[b] = 0.0f; }
        const float4* wr0 = (const float4*)(w2 + r0*64);
        const float4* wr1 = (const float4*)(w2 + r1*64);
        #pragma unroll 4
        for (int q = 0; q < 16; ++q) {
            float4 u = wr0[q], v = wr1[q];
            #pragma unroll
            for (int b = 0; b < BATCH; ++b) {
                const float* h = sh + b*64 + q*4;
                a0[b] += u.x*h[0] + u.y*h[1] + u.z*h[2] + u.w*h[3];
                a1[b] += v.x*h[0] + v.y*h[1] + v.z*h[2] + v.w*h[3];
            }
        }
        const float bi0 = b2[r0], bi1 = b2[r1];
        #pragma unroll
        for (int b = 0; b < BATCH; ++b)
            g_Wh[(size_t)(b*N_LAYERS + l)*WFULL + e3] =
                pack_bf16x2(a0[b] + bi0, a1[b] + bi1);
    } else {
        const int idx = (blockIdx.x - 384)*256 + tid;   // < 512
        const size_t c = (size_t)KC + idx;
        float acc[BATCH];
        #pragma unroll
        for (int b = 0; b < BATCH; ++b) acc[b] = 0.0f;
        const float4* wr = (const float4*)(w2 + c*64);
        #pragma unroll 4
        for (int q = 0; q < 16; ++q) {
            float4 w = wr[q];
            #pragma unroll
            for (int b = 0; b < BATCH; ++b) {
                const float* h = sh + b*64 + q*4;
                acc[b] += w.x*h[0] + w.y*h[1] + w.z*h[2] + w.w*h[3];
            }
        }
        const float bias = b2[c];
        #pragma unroll
        for (int b = 0; b < BATCH; ++b)
            g_bias[b*N_LAYERS*CH + idx] = acc[b] + bias;
    }
}

// =========================================================================
// FUSED 4-layer LVC conv (overlap-save). 512 threads, 1 CTA/SM.
// Per 128-t chunk: stage x (halo 16 -> 160 grid) into fp32 smem yf32,
// pack bf16x2 xbf; 4x { MMA (bf16), in-place fp32 residual epilogue,
// repack }. Only the final layer touches gmem output. W per layer staged
// from L2 via cp.async, overlapped with the previous epilogue.
// Warp (wr=wid&3 -> 32co, wc=wid>>2 -> 40t): mt=2 x nt=5.
// =========================================================================
#define SMEM_FUSED ((WFULL + CH*YSTR + 64*XBW) * 4)   /* 231424 B */

__global__ void __launch_bounds__(512, 1)
lvc_fused(const float* __restrict__ x, float* __restrict__ out,
          const float* __restrict__ alpha) {
    extern __shared__ __align__(16) uint32_t smem[];
    uint32_t* sW   = smem;                          // WFULL
    float*    yf32 = (float*)(smem + WFULL);        // 128 x YSTR
    uint32_t* xbf  = smem + WFULL + CH*YSTR;        // 64 x XBW

    const int b    = blockIdx.y;
    const int tid  = threadIdx.x;
    const int wid  = tid >> 5;
    const int lane = tid & 31;
    const int wr   = wid & 3;                       // co group (32)
    const int wc   = wid >> 2;                      // t group (40)

    const uint32_t dW = smem_u32(sW);
    const uint32_t dY = smem_u32(yf32);
    const float* xb = x + (size_t)b*CH*T_AUDIO;
    float*       ob = out + (size_t)b*CH*T_AUDIO;

    // per-thread output rows: cb = wr*2+mt, co = cb*16 + (lane>>2) + h*8
    float mybias[N_LAYERS][2][2];
    #pragma unroll
    for (int l = 0; l < N_LAYERS; ++l)
        #pragma unroll
        for (int mt = 0; mt < 2; ++mt)
            #pragma unroll
            for (int h = 0; h < 2; ++h)
                mybias[l][mt][h] = g_bias[(b*N_LAYERS + l)*CH
                                          + wr*32 + mt*16 + (lane >> 2) + h*8];
    float myal[2][2];
    #pragma unroll
    for (int mt = 0; mt < 2; ++mt)
        #pragma unroll
        for (int h = 0; h < 2; ++h)
            myal[mt][h] = alpha[wr*32 + mt*16 + (lane >> 2) + h*8];

    for (int tile = blockIdx.x; tile < TILES; tile += CTAS_X) {
        const int t0 = tile * NT;

        // ---- stage W0 + x chunk [t0-16, t0+144) ----
        {
            const uint32_t* Wg = g_Wh + (size_t)(b*N_LAYERS + 0)*WFULL;
            #pragma unroll
            for (int i = tid; i < WFULL/4; i += 512)
                cp16(dW + i*16, Wg + i*4);
        }
        if (t0 >= 16 && t0 + 144 <= T_AUDIO) {
            #pragma unroll
            for (int idx = tid; idx < CH*40; idx += 512) {
                const int row = idx / 40;
                const int ch  = idx - row*40;
                cp16(dY + (row*YSTR + ch*4)*4,
                     xb + (size_t)row*T_AUDIO + (t0 - 16) + ch*4);
            }
            CP_COMMIT();
            CP_WAIT0();
        } else {
            CP_COMMIT();
            for (int idx = tid; idx < CH*BUFW; idx += 512) {
                const int row = idx / BUFW;
                const int tl  = idx - row*BUFW;
                const int t   = t0 - 16 + tl;
                yf32[row*YSTR + tl] = (t >= 0 && t < T_AUDIO)
                                      ? xb[(size_t)row*T_AUDIO + t] : 0.0f;
            }
            CP_WAIT0();
        }
        __syncthreads();

        // ---- initial pack: x -> bf16x2 ----
        #pragma unroll
        for (int i = tid; i < 64*BUFW; i += 512) {
            const int pr = i / BUFW;
            const int tl = i - pr*BUFW;
            xbf[pr*XBW + 8 + tl] = pack_bf16x2(yf32[(2*pr)*YSTR + tl],
                                               yf32[(2*pr + 1)*YSTR + tl]);
        }
        __syncthreads();

        // ---- 4 layers ----
        #pragma unroll 1
        for (int l = 0; l < N_LAYERS; ++l) {
            const int dil = 1 << l;

            float acc[2][5][4];
            #pragma unroll
            for (int mt = 0; mt < 2; ++mt)
                #pragma unroll
                for (int n = 0; n < 5; ++n)
                    #pragma unroll
                    for (int q = 0; q < 4; ++q) acc[mt][n][q] = 0.0f;

            #pragma unroll 1
            for (int kk = 0; kk < 3; ++kk) {
                const int off = 8 + (kk - 1)*dil;
                #pragma unroll
                for (int ks8 = 0; ks8 < 8; ++ks8) {
                    const int ks   = kk*8 + ks8;
                    const int row0 = ks8*8 + (lane & 3);
                    const uint32_t* xrow = xbf + row0*XBW + wc*40 + (lane >> 2) + off;
                    uint32_t a[2][4];
                    #pragma unroll
                    for (int mt = 0; mt < 2; ++mt) {
                        const uint4 av = *(const uint4*)(sW + ((ks*8 + wr*2 + mt)*32 + lane)*4);
                        a[mt][0] = av.x; a[mt][1] = av.y; a[mt][2] = av.z; a[mt][3] = av.w;
                    }
                    #pragma unroll
                    for (int n = 0; n < 5; ++n) {
                        uint32_t bf[2];
                        bf[0] = xrow[n*8];
                        bf[1] = xrow[n*8 + 4*XBW];
                        MMA16(acc[0][n], a[0], bf);
                        MMA16(acc[1][n], a[1], bf);
                    }
                }
            }
            __syncthreads();   // all warps done reading sW + xbf

            if (l < 3) {       // prefetch next layer's W (overlaps epilogue)
                const uint32_t* Wg = g_Wh + (size_t)(b*N_LAYERS + l + 1)*WFULL;
                #pragma unroll
                for (int i = tid; i < WFULL/4; i += 512)
                    cp16(dW + i*16, Wg + i*4);
                CP_COMMIT();
            }

            // ---- epilogue: residual in smem, in-place; repack or final out ----
            #pragma unroll
            for (int mt = 0; mt < 2; ++mt) {
                #pragma unroll
                for (int n = 0; n < 5; ++n) {
                    const int c0 = wc*40 + n*8 + (lane & 3)*2;
                    float y[2][2];
                    #pragma unroll
                    for (int h = 0; h < 2; ++h) {
                        const int cog = wr*32 + mt*16 + (lane >> 2) + h*8;
                        const float2 xv = *(const float2*)&yf32[cog*YSTR + c0];
                        y[h][0] = acc[mt][n][h*2+0] + mybias[l][mt][h] + xv.x;
                        y[h][1] = acc[mt][n][h*2+1] + mybias[l][mt][h] + xv.y;
                    }
                    if (l < 3) {
                        #pragma unroll
                        for (int h = 0; h < 2; ++h) {
                            const int cog = wr*32 + mt*16 + (lane >> 2) + h*8;
                            float2 v; v.x = y[h][0]; v.y = y[h][1];
                            *(float2*)&yf32[cog*YSTR + c0] = v;
                            const float o0 = __shfl_xor_sync(0xffffffffu, y[h][0], 4);
                            const float o1 = __shfl_xor_sync(0xffffffffu, y[h][1], 4);
                            if ((lane & 4) == 0) {
                                uint2 w;
                                w.x = pack_bf16x2(y[h][0], o0);
                                w.y = pack_bf16x2(y[h][1], o1);
                                *(uint2*)&xbf[(cog >> 1)*XBW + 8 + c0] = w;
                            }
                        }
                    } else if (c0 >= 16 && c0 < 144) {   // whole 8-block in/out
                        #pragma unroll
                        for (int h = 0; h < 2; ++h) {
                            const int cog = wr*32 + mt*16 + (lane >> 2) + h*8;
                            const float a = myal[mt][h];
                            const float inva = 1.0f/(a + 1e-8f);
                            float s0 = sinf(a*y[h][0]), s1 = sinf(a*y[h][1]);
                            float2 v;
                            v.x = y[h][0] + inva*s0*s0;
                            v.y = y[h][1] + inva*s1*s1;
                            *(float2*)&ob[(size_t)cog*T_AUDIO + t0 + (c0 - 16)] = v;
                        }
                    }
                }
            }
            if (l < 3) CP_WAIT0();
            __syncthreads();
        }
    }
}

// =========================================================================
extern "C" void kernel_launch(void* const* d_in, const int* in_sizes, int n_in,
                              void* d_out, int out_size) {
    const float* x     = (const float*)d_in[0];
    const float* cond  = (const float*)d_in[1];
    const float* w0    = (const float*)d_in[2];
    const float* b0    = (const float*)d_in[3];
    const float* w1    = (const float*)d_in[4];
    const float* b1    = (const float*)d_in[5];
    const float* w2    = (const float*)d_in[6];
    const float* b2    = (const float*)d_in[7];
    const float* alpha = (const float*)d_in[8];
    float* out = (float*)d_out;

    const int smemA = (COND_CH*T_MEL + 64*COND_CH*5 + 64*64*3 + 64*T_MEL + 64*T_MEL)
                      * (int)sizeof(float);
    cudaFuncSetAttribute(condnet_kernel, cudaFuncAttributeMaxDynamicSharedMemorySize, smemA);
    condnet_kernel<<<BATCH, 256, smemA>>>(cond, w0, b0, w1, b1);

    weights_kernel<<<386, 256>>>(w2, b2);

    cudaFuncSetAttribute(lvc_fused, cudaFuncAttributeMaxDynamicSharedMemorySize, SMEM_FUSED);
    dim3 grid(CTAS_X, BATCH);
    lvc_fused<<<grid, 512, SMEM_FUSED>>>(x, out, alpha);
}

// round 11
// speedup vs baseline: 1.6494x; 1.1205x over previous
#include <cuda_runtime.h>
#include <math.h>
#include <stdint.h>

#define BATCH    8
#define CH       128
#define T_AUDIO  16384
#define COND_CH  80
#define T_MEL    32
#define N_LAYERS 4
#define KPL      (CH*CH*3)        /* 49152 */
#define KC       (KPL*N_LAYERS)   /* 196608 */
#define BC       (CH*N_LAYERS)    /* 512 */

#define NT       128              /* output chunk */
#define TILES    (T_AUDIO/NT)     /* 128 */
#define NCTAS    148              /* flattened persistent grid */
#define WFULL    24576            /* per (b,l): 192 frag-rows x 32 lanes x 4 words */
#define BUFW     160              /* compute grid width (chunk + 2*16 halo) */
#define YSTR     168              /* yf32 stride: 168%32==8 -> conflict-free 64b phases */
#define XBW      184              /* xbf stride: 184%32==24 -> B frags conflict-free */

// ---------------- device scratch ----------------
__device__ float    g_hmean[BATCH*64];
__device__ uint32_t g_Wh[BATCH*N_LAYERS*WFULL];
__device__ float    g_bias[BATCH*N_LAYERS*CH];

__device__ __forceinline__ float gelu_exact(float x) {
    return 0.5f * x * (1.0f + erff(x * 0.7071067811865475f));
}
__device__ __forceinline__ uint32_t pack_bf16x2(float lo, float hi) {
    uint32_t u;
    asm("cvt.rn.bf16x2.f32 %0, %1, %2;" : "=r"(u) : "f"(hi), "f"(lo));
    return u;
}
__device__ __forceinline__ uint32_t smem_u32(const void* p) {
    uint32_t a;
    asm("{ .reg .u64 t; cvta.to.shared.u64 t, %1; cvt.u32.u64 %0, t; }" : "=r"(a) : "l"(p));
    return a;
}
__device__ __forceinline__ void cp16(uint32_t dst, const void* src) {
    asm volatile("cp.async.cg.shared.global [%0], [%1], 16;" :: "r"(dst), "l"(src));
}
#define CP_COMMIT() asm volatile("cp.async.commit_group;" ::: "memory")
#define CP_WAIT0()  asm volatile("cp.async.wait_group 0;" ::: "memory")

#define MMA16(d_, a_, b_) \
  asm volatile("mma.sync.aligned.m16n8k16.row.col.f32.bf16.bf16.f32 " \
    "{%0,%1,%2,%3}, {%4,%5,%6,%7}, {%8,%9}, {%0,%1,%2,%3};" \
    : "+f"((d_)[0]), "+f"((d_)[1]), "+f"((d_)[2]), "+f"((d_)[3]) \
    : "r"((a_)[0]), "r"((a_)[1]), "r"((a_)[2]), "r"((a_)[3]), \
      "r"((b_)[0]), "r"((b_)[1]))

// =========================================================================
// Kernel A: conditioning net v2. Weights staged TRANSPOSED ([m][o], o-minor)
// so the inner loop is 2x broadcast LDS.128 + 1 LDS per (i,k) step.
// =========================================================================
#define SW0T_N (COND_CH*5*64)     /* 25600 */
#define SW1T_N (64*3*64)          /* 12288 */

__global__ void condnet_kernel(const float* __restrict__ cond,
                               const float* __restrict__ w0, const float* __restrict__ b0,
                               const float* __restrict__ w1, const float* __restrict__ b1) {
    extern __shared__ float smemf[];
    float* sc   = smemf;                     // 80*32
    float* sw0t = sc   + COND_CH*T_MEL;      // [m=i*5+k][o]
    float* sw1t = sw0t + SW0T_N;             // [m=i*3+k][o]
    float* sh0  = sw1t + SW1T_N;             // 64*32
    float* sh1  = sh0  + 64*T_MEL;           // 64*32

    const int b = blockIdx.x;
    const int tid = threadIdx.x;             // 256

    for (int i = tid; i < COND_CH*T_MEL; i += 256) sc[i] = cond[b*COND_CH*T_MEL + i];
    // transposed weight staging: consecutive tid -> consecutive o (STS conflict-free)
    for (int idx = tid; idx < SW0T_N; idx += 256) {
        const int m = idx >> 6, o = idx & 63;
        sw0t[idx] = w0[o*(COND_CH*5) + m];
    }
    for (int idx = tid; idx < SW1T_N; idx += 256) {
        const int m = idx >> 6, o = idx & 63;
        sw1t[idx] = w1[o*(64*3) + m];
    }
    __syncthreads();

    const int og = tid >> 5;   // 0..7  (8 channels each)
    const int t  = tid & 31;

    float acc[8];
    #pragma unroll
    for (int r = 0; r < 8; ++r) acc[r] = b0[og*8 + r];
    for (int i = 0; i < COND_CH; ++i) {
        #pragma unroll
        for (int k = 0; k < 5; ++k) {
            const int tt = t + k - 2;
            if (tt >= 0 && tt < T_MEL) {
                const float xv = sc[i*T_MEL + tt];
                const float4 wA = *(const float4*)&sw0t[(i*5 + k)*64 + og*8];
                const float4 wB = *(const float4*)&sw0t[(i*5 + k)*64 + og*8 + 4];
                acc[0] += wA.x*xv; acc[1] += wA.y*xv; acc[2] += wA.z*xv; acc[3] += wA.w*xv;
                acc[4] += wB.x*xv; acc[5] += wB.y*xv; acc[6] += wB.z*xv; acc[7] += wB.w*xv;
            }
        }
    }
    #pragma unroll
    for (int r = 0; r < 8; ++r) sh0[(og*8 + r)*T_MEL + t] = gelu_exact(acc[r]);
    __syncthreads();

    #pragma unroll
    for (int r = 0; r < 8; ++r) acc[r] = b1[og*8 + r];
    for (int i = 0; i < 64; ++i) {
        #pragma unroll
        for (int k = 0; k < 3; ++k) {
            const int tt = t + k - 1;
            if (tt >= 0 && tt < T_MEL) {
                const float xv = sh0[i*T_MEL + tt];
                const float4 wA = *(const float4*)&sw1t[(i*3 + k)*64 + og*8];
                const float4 wB = *(const float4*)&sw1t[(i*3 + k)*64 + og*8 + 4];
                acc[0] += wA.x*xv; acc[1] += wA.y*xv; acc[2] += wA.z*xv; acc[3] += wA.w*xv;
                acc[4] += wB.x*xv; acc[5] += wB.y*xv; acc[6] += wB.z*xv; acc[7] += wB.w*xv;
            }
        }
    }
    #pragma unroll
    for (int r = 0; r < 8; ++r) sh1[(og*8 + r)*T_MEL + t] = gelu_exact(acc[r]);
    __syncthreads();

    if (tid < 64) {
        float s = 0.0f;
        #pragma unroll
        for (int tt = 0; tt < T_MEL; ++tt) s += sh1[tid*T_MEL + tt];
        g_hmean[b*64 + tid] = s * (1.0f/T_MEL);
    }
}

// =========================================================================
// Kernel B: LVC weights -> bf16x2 fragment-major (unchanged)
// =========================================================================
__global__ void weights_kernel(const float* __restrict__ w2,
                               const float* __restrict__ b2) {
    __shared__ float sh[BATCH*64];
    const int tid = threadIdx.x;
    for (int i = tid; i < BATCH*64; i += 256) sh[i] = g_hmean[i];
    __syncthreads();

    if (blockIdx.x < 384) {
        const int gidx = blockIdx.x*256 + tid;     // < 98304
        const int l    = gidx / WFULL;
        const int e3   = gidx - l*WFULL;
        const int j    = e3 & 3;
        const int lane = (e3 >> 2) & 31;
        const int cb   = (e3 >> 7) & 7;
        const int ks   = e3 >> 10;
        const int co   = cb*16 + (lane >> 2) + (j & 1)*8;
        const int kl0  = (lane & 3)*2 + ((j >> 1) & 1)*8;
        const int kg0  = ks*16 + kl0;
        const int kk   = kg0 >> 7;
        const int ci0  = kg0 & 127;
        const size_t r0 = (size_t)l*KPL + (size_t)co*384 + ci0*3 + kk;
        const size_t r1 = r0 + 3;

        float a0[BATCH], a1[BATCH];
        #pragma unroll
        for (int b = 0; b < BATCH; ++b) { a0[b] = 0.0f; a1[b] = 0.0f; }
        const float4* wr0 = (const float4*)(w2 + r0*64);
        const float4* wr1 = (const float4*)(w2 + r1*64);
        #pragma unroll 4
        for (int q = 0; q < 16; ++q) {
            float4 u = wr0[q], v = wr1[q];
            #pragma unroll
            for (int b = 0; b < BATCH; ++b) {
                const float* h = sh + b*64 + q*4;
                a0[b] += u.x*h[0] + u.y*h[1] + u.z*h[2] + u.w*h[3];
                a1[b] += v.x*h[0] + v.y*h[1] + v.z*h[2] + v.w*h[3];
            }
        }
        const float bi0 = b2[r0], bi1 = b2[r1];
        #pragma unroll
        for (int b = 0; b < BATCH; ++b)
            g_Wh[(size_t)(b*N_LAYERS + l)*WFULL + e3] =
                pack_bf16x2(a0[b] + bi0, a1[b] + bi1);
    } else {
        const int idx = (blockIdx.x - 384)*256 + tid;   // < 512
        const size_t c = (size_t)KC + idx;
        float acc[BATCH];
        #pragma unroll
        for (int b = 0; b < BATCH; ++b) acc[b] = 0.0f;
        const float4* wr = (const float4*)(w2 + c*64);
        #pragma unroll 4
        for (int q = 0; q < 16; ++q) {
            float4 w = wr[q];
            #pragma unroll
            for (int b = 0; b < BATCH; ++b) {
                const float* h = sh + b*64 + q*4;
                acc[b] += w.x*h[0] + w.y*h[1] + w.z*h[2] + w.w*h[3];
            }
        }
        const float bias = b2[c];
        #pragma unroll
        for (int b = 0; b < BATCH; ++b)
            g_bias[b*N_LAYERS*CH + idx] = acc[b] + bias;
    }
}

// =========================================================================
// FUSED 4-layer LVC conv (overlap-save), flattened persistent grid:
// 148 CTAs loop over all 1024 (b,tile) work items -> makespan 7 tiles.
// =========================================================================
#define SMEM_FUSED ((WFULL + CH*YSTR + 64*XBW) * 4)   /* 231424 B */

__global__ void __launch_bounds__(512, 1)
lvc_fused(const float* __restrict__ x, float* __restrict__ out,
          const float* __restrict__ alpha) {
    extern __shared__ __align__(16) uint32_t smem[];
    uint32_t* sW   = smem;                          // WFULL
    float*    yf32 = (float*)(smem + WFULL);        // 128 x YSTR
    uint32_t* xbf  = smem + WFULL + CH*YSTR;        // 64 x XBW

    const int tid  = threadIdx.x;
    const int wid  = tid >> 5;
    const int lane = tid & 31;
    const int wr   = wid & 3;                       // co group (32)
    const int wc   = wid >> 2;                      // t group (40)

    const uint32_t dW = smem_u32(sW);
    const uint32_t dY = smem_u32(yf32);

    float myal[2][2];
    #pragma unroll
    for (int mt = 0; mt < 2; ++mt)
        #pragma unroll
        for (int h = 0; h < 2; ++h)
            myal[mt][h] = alpha[wr*32 + mt*16 + (lane >> 2) + h*8];

    for (int g = blockIdx.x; g < BATCH*TILES; g += NCTAS) {
        const int b    = g >> 7;
        const int tile = g & (TILES - 1);
        const int t0   = tile * NT;
        const float* xb = x   + (size_t)b*CH*T_AUDIO;
        float*       ob = out + (size_t)b*CH*T_AUDIO;

        float mybias[N_LAYERS][2][2];
        #pragma unroll
        for (int l = 0; l < N_LAYERS; ++l)
            #pragma unroll
            for (int mt = 0; mt < 2; ++mt)
                #pragma unroll
                for (int h = 0; h < 2; ++h)
                    mybias[l][mt][h] = g_bias[(b*N_LAYERS + l)*CH
                                              + wr*32 + mt*16 + (lane >> 2) + h*8];

        // ---- stage W0 + x chunk [t0-16, t0+144) ----
        {
            const uint32_t* Wg = g_Wh + (size_t)(b*N_LAYERS + 0)*WFULL;
            #pragma unroll
            for (int i = tid; i < WFULL/4; i += 512)
                cp16(dW + i*16, Wg + i*4);
        }
        if (t0 >= 16 && t0 + 144 <= T_AUDIO) {
            #pragma unroll
            for (int idx = tid; idx < CH*40; idx += 512) {
                const int row = idx / 40;
                const int ch  = idx - row*40;
                cp16(dY + (row*YSTR + ch*4)*4,
                     xb + (size_t)row*T_AUDIO + (t0 - 16) + ch*4);
            }
            CP_COMMIT();
            CP_WAIT0();
        } else {
            CP_COMMIT();
            for (int idx = tid; idx < CH*BUFW; idx += 512) {
                const int row = idx / BUFW;
                const int tl  = idx - row*BUFW;
                const int t   = t0 - 16 + tl;
                yf32[row*YSTR + tl] = (t >= 0 && t < T_AUDIO)
                                      ? xb[(size_t)row*T_AUDIO + t] : 0.0f;
            }
            CP_WAIT0();
        }
        __syncthreads();

        // ---- initial pack: x -> bf16x2 ----
        #pragma unroll
        for (int i = tid; i < 64*BUFW; i += 512) {
            const int pr = i / BUFW;
            const int tl = i - pr*BUFW;
            xbf[pr*XBW + 8 + tl] = pack_bf16x2(yf32[(2*pr)*YSTR + tl],
                                               yf32[(2*pr + 1)*YSTR + tl]);
        }
        __syncthreads();

        // ---- 4 layers ----
        #pragma unroll 1
        for (int l = 0; l < N_LAYERS; ++l) {
            const int dil = 1 << l;

            float acc[2][5][4];
            #pragma unroll
            for (int mt = 0; mt < 2; ++mt)
                #pragma unroll
                for (int n = 0; n < 5; ++n)
                    #pragma unroll
                    for (int q = 0; q < 4; ++q) acc[mt][n][q] = 0.0f;

            #pragma unroll 1
            for (int kk = 0; kk < 3; ++kk) {
                const int off = 8 + (kk - 1)*dil;
                #pragma unroll
                for (int ks8 = 0; ks8 < 8; ++ks8) {
                    const int ks   = kk*8 + ks8;
                    const int row0 = ks8*8 + (lane & 3);
                    const uint32_t* xrow = xbf + row0*XBW + wc*40 + (lane >> 2) + off;
                    uint32_t a[2][4];
                    #pragma unroll
                    for (int mt = 0; mt < 2; ++mt) {
                        const uint4 av = *(const uint4*)(sW + ((ks*8 + wr*2 + mt)*32 + lane)*4);
                        a[mt][0] = av.x; a[mt][1] = av.y; a[mt][2] = av.z; a[mt][3] = av.w;
                    }
                    #pragma unroll
                    for (int n = 0; n < 5; ++n) {
                        uint32_t bf[2];
                        bf[0] = xrow[n*8];
                        bf[1] = xrow[n*8 + 4*XBW];
                        MMA16(acc[0][n], a[0], bf);
                        MMA16(acc[1][n], a[1], bf);
                    }
                }
            }
            __syncthreads();   // all warps done reading sW + xbf

            if (l < 3) {       // prefetch next layer's W (overlaps epilogue)
                const uint32_t* Wg = g_Wh + (size_t)(b*N_LAYERS + l + 1)*WFULL;
                #pragma unroll
                for (int i = tid; i < WFULL/4; i += 512)
                    cp16(dW + i*16, Wg + i*4);
                CP_COMMIT();
            }

            // ---- epilogue: residual in smem, in-place; repack or final out ----
            #pragma unroll
            for (int mt = 0; mt < 2; ++mt) {
                #pragma unroll
                for (int n = 0; n < 5; ++n) {
                    const int c0 = wc*40 + n*8 + (lane & 3)*2;
                    float y[2][2];
                    #pragma unroll
                    for (int h = 0; h < 2; ++h) {
                        const int cog = wr*32 + mt*16 + (lane >> 2) + h*8;
                        const float2 xv = *(const float2*)&yf32[cog*YSTR + c0];
                        y[h][0] = acc[mt][n][h*2+0] + mybias[l][mt][h] + xv.x;
                        y[h][1] = acc[mt][n][h*2+1] + mybias[l][mt][h] + xv.y;
                    }
                    if (l < 3) {
                        #pragma unroll
                        for (int h = 0; h < 2; ++h) {
                            const int cog = wr*32 + mt*16 + (lane >> 2) + h*8;
                            float2 v; v.x = y[h][0]; v.y = y[h][1];
                            *(float2*)&yf32[cog*YSTR + c0] = v;
                            const float o0 = __shfl_xor_sync(0xffffffffu, y[h][0], 4);
                            const float o1 = __shfl_xor_sync(0xffffffffu, y[h][1], 4);
                            if ((lane & 4) == 0) {
                                uint2 w;
                                w.x = pack_bf16x2(y[h][0], o0);
                                w.y = pack_bf16x2(y[h][1], o1);
                                *(uint2*)&xbf[(cog >> 1)*XBW + 8 + c0] = w;
                            }
                        }
                    } else if (c0 >= 16 && c0 < 144) {
                        #pragma unroll
                        for (int h = 0; h < 2; ++h) {
                            const int cog = wr*32 + mt*16 + (lane >> 2) + h*8;
                            const float a = myal[mt][h];
                            const float inva = 1.0f/(a + 1e-8f);
                            float s0 = sinf(a*y[h][0]), s1 = sinf(a*y[h][1]);
                            float2 v;
                            v.x = y[h][0] + inva*s0*s0;
                            v.y = y[h][1] + inva*s1*s1;
                            *(float2*)&ob[(size_t)cog*T_AUDIO + t0 + (c0 - 16)] = v;
                        }
                    }
                }
            }
            if (l < 3) CP_WAIT0();
            __syncthreads();
        }
    }
}

// =========================================================================
extern "C" void kernel_launch(void* const* d_in, const int* in_sizes, int n_in,
                              void* d_out, int out_size) {
    const float* x     = (const float*)d_in[0];
    const float* cond  = (const float*)d_in[1];
    const float* w0    = (const float*)d_in[2];
    const float* b0    = (const float*)d_in[3];
    const float* w1    = (const float*)d_in[4];
    const float* b1    = (const float*)d_in[5];
    const float* w2    = (const float*)d_in[6];
    const float* b2    = (const float*)d_in[7];
    const float* alpha = (const float*)d_in[8];
    float* out = (float*)d_out;

    const int smemA = (COND_CH*T_MEL + SW0T_N + SW1T_N + 64*T_MEL + 64*T_MEL)
                      * (int)sizeof(float);
    cudaFuncSetAttribute(condnet_kernel, cudaFuncAttributeMaxDynamicSharedMemorySize, smemA);
    condnet_kernel<<<BATCH, 256, smemA>>>(cond, w0, b0, w1, b1);

    weights_kernel<<<386, 256>>>(w2, b2);

    cudaFuncSetAttribute(lvc_fused, cudaFuncAttributeMaxDynamicSharedMemorySize, SMEM_FUSED);
    lvc_fused<<<NCTAS, 512, SMEM_FUSED>>>(x, out, alpha);
}

// round 12
// speedup vs baseline: 1.6897x; 1.0244x over previous
#include <cuda_runtime.h>
#include <math.h>
#include <stdint.h>

#define BATCH    8
#define CH       128
#define T_AUDIO  16384
#define COND_CH  80
#define T_MEL    32
#define N_LAYERS 4
#define KPL      (CH*CH*3)        /* 49152 */
#define KC       (KPL*N_LAYERS)   /* 196608 */
#define BC       (CH*N_LAYERS)    /* 512 */

#define NT       128              /* output chunk */
#define TILES    (T_AUDIO/NT)     /* 128 */
#define NCTAS    148              /* flattened persistent grid */
#define WFULL    24576            /* per (b,l): 192 frag-rows x 32 lanes x 4 words */
#define BUFW     160              /* compute grid width (chunk + 2*16 halo) */
#define YSTR     168              /* yf32 stride: 168%32==8 -> conflict-free 64b phases */
#define XBW      184              /* xbf stride: 184%32==24 -> B frags conflict-free */

// ---------------- device scratch ----------------
__device__ float    g_hmean[BATCH*64];
__device__ uint32_t g_Wh[BATCH*N_LAYERS*WFULL];
__device__ float    g_bias[BATCH*N_LAYERS*CH];

__device__ __forceinline__ float gelu_exact(float x) {
    return 0.5f * x * (1.0f + erff(x * 0.7071067811865475f));
}
__device__ __forceinline__ uint32_t pack_bf16x2(float lo, float hi) {
    uint32_t u;
    asm("cvt.rn.bf16x2.f32 %0, %1, %2;" : "=r"(u) : "f"(hi), "f"(lo));
    return u;
}
__device__ __forceinline__ uint32_t smem_u32(const void* p) {
    uint32_t a;
    asm("{ .reg .u64 t; cvta.to.shared.u64 t, %1; cvt.u32.u64 %0, t; }" : "=r"(a) : "l"(p));
    return a;
}
__device__ __forceinline__ void cp16(uint32_t dst, const void* src) {
    asm volatile("cp.async.cg.shared.global [%0], [%1], 16;" :: "r"(dst), "l"(src));
}
#define CP_COMMIT() asm volatile("cp.async.commit_group;" ::: "memory")
#define CP_WAIT0()  asm volatile("cp.async.wait_group 0;" ::: "memory")

#define MMA16(d_, a_, b_) \
  asm volatile("mma.sync.aligned.m16n8k16.row.col.f32.bf16.bf16.f32 " \
    "{%0,%1,%2,%3}, {%4,%5,%6,%7}, {%8,%9}, {%0,%1,%2,%3};" \
    : "+f"((d_)[0]), "+f"((d_)[1]), "+f"((d_)[2]), "+f"((d_)[3]) \
    : "r"((a_)[0]), "r"((a_)[1]), "r"((a_)[2]), "r"((a_)[3]), \
      "r"((b_)[0]), "r"((b_)[1]))

// =========================================================================
// Kernel A: conditioning net v3. 1024 threads: 32 warps, each owns 2
// channels -> 4x less work/warp + 4x more warps for latency hiding.
// Weights staged transposed ([m][o], o-minor) -> broadcast LDS.64.
// =========================================================================
#define SW0T_N (COND_CH*5*64)     /* 25600 */
#define SW1T_N (64*3*64)          /* 12288 */

__global__ void __launch_bounds__(1024)
condnet_kernel(const float* __restrict__ cond,
               const float* __restrict__ w0, const float* __restrict__ b0,
               const float* __restrict__ w1, const float* __restrict__ b1) {
    extern __shared__ float smemf[];
    float* sc   = smemf;                     // 80*32
    float* sw0t = sc   + COND_CH*T_MEL;      // [m=i*5+k][o]
    float* sw1t = sw0t + SW0T_N;             // [m=i*3+k][o]
    float* sh0  = sw1t + SW1T_N;             // 64*32
    float* sh1  = sh0  + 64*T_MEL;           // 64*32

    const int b = blockIdx.x;
    const int tid = threadIdx.x;             // 1024

    for (int i = tid; i < COND_CH*T_MEL; i += 1024) sc[i] = cond[b*COND_CH*T_MEL + i];
    for (int idx = tid; idx < SW0T_N; idx += 1024) {
        const int m = idx >> 6, o = idx & 63;
        sw0t[idx] = w0[o*(COND_CH*5) + m];
    }
    for (int idx = tid; idx < SW1T_N; idx += 1024) {
        const int m = idx >> 6, o = idx & 63;
        sw1t[idx] = w1[o*(64*3) + m];
    }
    __syncthreads();

    const int og = tid >> 5;   // 0..31 (2 channels each)
    const int t  = tid & 31;

    float a0 = b0[og*2], a1 = b0[og*2 + 1];
    for (int i = 0; i < COND_CH; ++i) {
        #pragma unroll
        for (int k = 0; k < 5; ++k) {
            const int tt = t + k - 2;
            if (tt >= 0 && tt < T_MEL) {
                const float xv = sc[i*T_MEL + tt];
                const float2 w = *(const float2*)&sw0t[(i*5 + k)*64 + og*2];
                a0 += w.x*xv; a1 += w.y*xv;
            }
        }
    }
    sh0[(og*2    )*T_MEL + t] = gelu_exact(a0);
    sh0[(og*2 + 1)*T_MEL + t] = gelu_exact(a1);
    __syncthreads();

    a0 = b1[og*2]; a1 = b1[og*2 + 1];
    for (int i = 0; i < 64; ++i) {
        #pragma unroll
        for (int k = 0; k < 3; ++k) {
            const int tt = t + k - 1;
            if (tt >= 0 && tt < T_MEL) {
                const float xv = sh0[i*T_MEL + tt];
                const float2 w = *(const float2*)&sw1t[(i*3 + k)*64 + og*2];
                a0 += w.x*xv; a1 += w.y*xv;
            }
        }
    }
    sh1[(og*2    )*T_MEL + t] = gelu_exact(a0);
    sh1[(og*2 + 1)*T_MEL + t] = gelu_exact(a1);
    __syncthreads();

    if (tid < 64) {
        float s = 0.0f;
        #pragma unroll
        for (int tt = 0; tt < T_MEL; ++tt) s += sh1[tid*T_MEL + tt];
        g_hmean[b*64 + tid] = s * (1.0f/T_MEL);
    }
}

// =========================================================================
// Kernel B: LVC weights -> bf16x2 fragment-major (unchanged)
// =========================================================================
__global__ void weights_kernel(const float* __restrict__ w2,
                               const float* __restrict__ b2) {
    __shared__ float sh[BATCH*64];
    const int tid = threadIdx.x;
    for (int i = tid; i < BATCH*64; i += 256) sh[i] = g_hmean[i];
    __syncthreads();

    if (blockIdx.x < 384) {
        const int gidx = blockIdx.x*256 + tid;     // < 98304
        const int l    = gidx / WFULL;
        const int e3   = gidx - l*WFULL;
        const int j    = e3 & 3;
        const int lane = (e3 >> 2) & 31;
        const int cb   = (e3 >> 7) & 7;
        const int ks   = e3 >> 10;
        const int co   = cb*16 + (lane >> 2) + (j & 1)*8;
        const int kl0  = (lane & 3)*2 + ((j >> 1) & 1)*8;
        const int kg0  = ks*16 + kl0;
        const int kk   = kg0 >> 7;
        const int ci0  = kg0 & 127;
        const size_t r0 = (size_t)l*KPL + (size_t)co*384 + ci0*3 + kk;
        const size_t r1 = r0 + 3;

        float a0[BATCH], a1[BATCH];
        #pragma unroll
        for (int b = 0; b < BATCH; ++b) { a0[b] = 0.0f; a1[b] = 0.0f; }
        const float4* wr0 = (const float4*)(w2 + r0*64);
        const float4* wr1 = (const float4*)(w2 + r1*64);
        #pragma unroll 4
        for (int q = 0; q < 16; ++q) {
            float4 u = wr0[q], v = wr1[q];
            #pragma unroll
            for (int b = 0; b < BATCH; ++b) {
                const float* h = sh + b*64 + q*4;
                a0[b] += u.x*h[0] + u.y*h[1] + u.z*h[2] + u.w*h[3];
                a1[b] += v.x*h[0] + v.y*h[1] + v.z*h[2] + v.w*h[3];
            }
        }
        const float bi0 = b2[r0], bi1 = b2[r1];
        #pragma unroll
        for (int b = 0; b < BATCH; ++b)
            g_Wh[(size_t)(b*N_LAYERS + l)*WFULL + e3] =
                pack_bf16x2(a0[b] + bi0, a1[b] + bi1);
    } else {
        const int idx = (blockIdx.x - 384)*256 + tid;   // < 512
        const size_t c = (size_t)KC + idx;
        float acc[BATCH];
        #pragma unroll
        for (int b = 0; b < BATCH; ++b) acc[b] = 0.0f;
        const float4* wr = (const float4*)(w2 + c*64);
        #pragma unroll 4
        for (int q = 0; q < 16; ++q) {
            float4 w = wr[q];
            #pragma unroll
            for (int b = 0; b < BATCH; ++b) {
                const float* h = sh + b*64 + q*4;
                acc[b] += w.x*h[0] + w.y*h[1] + w.z*h[2] + w.w*h[3];
            }
        }
        const float bias = b2[c];
        #pragma unroll
        for (int b = 0; b < BATCH; ++b)
            g_bias[b*N_LAYERS*CH + idx] = acc[b] + bias;
    }
}

// =========================================================================
// FUSED 4-layer LVC conv, residual carried in REGISTERS (fragment positions
// are layer-invariant). yf32 is staging-only; per-layer epilogue = regs +
// bf16x2 repack STS. 148 persistent CTAs over 1024 (b,tile) items.
// =========================================================================
#define SMEM_FUSED ((WFULL + CH*YSTR + 64*XBW) * 4)   /* 231424 B */

__global__ void __launch_bounds__(512, 1)
lvc_fused(const float* __restrict__ x, float* __restrict__ out,
          const float* __restrict__ alpha) {
    extern __shared__ __align__(16) uint32_t smem[];
    uint32_t* sW   = smem;                          // WFULL
    float*    yf32 = (float*)(smem + WFULL);        // 128 x YSTR (staging only)
    uint32_t* xbf  = smem + WFULL + CH*YSTR;        // 64 x XBW

    const int tid  = threadIdx.x;
    const int wid  = tid >> 5;
    const int lane = tid & 31;
    const int wr   = wid & 3;                       // co group (32)
    const int wc   = wid >> 2;                      // t group (40)

    const uint32_t dW = smem_u32(sW);
    const uint32_t dY = smem_u32(yf32);

    for (int g = blockIdx.x; g < BATCH*TILES; g += NCTAS) {
        const int b    = g >> 7;
        const int tile = g & (TILES - 1);
        const int t0   = tile * NT;
        const float* xb = x   + (size_t)b*CH*T_AUDIO;
        float*       ob = out + (size_t)b*CH*T_AUDIO;

        // ---- stage W0 + x chunk [t0-16, t0+144) ----
        {
            const uint32_t* Wg = g_Wh + (size_t)(b*N_LAYERS + 0)*WFULL;
            #pragma unroll
            for (int i = tid; i < WFULL/4; i += 512)
                cp16(dW + i*16, Wg + i*4);
        }
        if (t0 >= 16 && t0 + 144 <= T_AUDIO) {
            #pragma unroll
            for (int idx = tid; idx < CH*40; idx += 512) {
                const int row = idx / 40;
                const int ch  = idx - row*40;
                cp16(dY + (row*YSTR + ch*4)*4,
                     xb + (size_t)row*T_AUDIO + (t0 - 16) + ch*4);
            }
            CP_COMMIT();
            CP_WAIT0();
        } else {
            CP_COMMIT();
            for (int idx = tid; idx < CH*BUFW; idx += 512) {
                const int row = idx / BUFW;
                const int tl  = idx - row*BUFW;
                const int t   = t0 - 16 + tl;
                yf32[row*YSTR + tl] = (t >= 0 && t < T_AUDIO)
                                      ? xb[(size_t)row*T_AUDIO + t] : 0.0f;
            }
            CP_WAIT0();
        }
        __syncthreads();

        // ---- initial pack (x -> bf16x2) + load residual regs ----
        #pragma unroll
        for (int i = tid; i < 64*BUFW; i += 512) {
            const int pr = i / BUFW;
            const int tl = i - pr*BUFW;
            xbf[pr*XBW + 8 + tl] = pack_bf16x2(yf32[(2*pr)*YSTR + tl],
                                               yf32[(2*pr + 1)*YSTR + tl]);
        }
        float res[2][5][4];
        #pragma unroll
        for (int mt = 0; mt < 2; ++mt) {
            #pragma unroll
            for (int n = 0; n < 5; ++n) {
                const int c0 = wc*40 + n*8 + (lane & 3)*2;
                #pragma unroll
                for (int h = 0; h < 2; ++h) {
                    const int cog = wr*32 + mt*16 + (lane >> 2) + h*8;
                    const float2 xv = *(const float2*)&yf32[cog*YSTR + c0];
                    res[mt][n][h*2+0] = xv.x;
                    res[mt][n][h*2+1] = xv.y;
                }
            }
        }
        __syncthreads();

        // ---- 4 layers ----
        #pragma unroll 1
        for (int l = 0; l < N_LAYERS; ++l) {
            const int dil = 1 << l;

            float bias_l[2][2];
            #pragma unroll
            for (int mt = 0; mt < 2; ++mt)
                #pragma unroll
                for (int h = 0; h < 2; ++h)
                    bias_l[mt][h] = g_bias[(b*N_LAYERS + l)*CH
                                           + wr*32 + mt*16 + (lane >> 2) + h*8];

            float acc[2][5][4];
            #pragma unroll
            for (int mt = 0; mt < 2; ++mt)
                #pragma unroll
                for (int n = 0; n < 5; ++n)
                    #pragma unroll
                    for (int q = 0; q < 4; ++q) acc[mt][n][q] = 0.0f;

            #pragma unroll 1
            for (int kk = 0; kk < 3; ++kk) {
                const int off = 8 + (kk - 1)*dil;
                #pragma unroll
                for (int ks8 = 0; ks8 < 8; ++ks8) {
                    const int ks   = kk*8 + ks8;
                    const int row0 = ks8*8 + (lane & 3);
                    const uint32_t* xrow = xbf + row0*XBW + wc*40 + (lane >> 2) + off;
                    uint32_t a[2][4];
                    #pragma unroll
                    for (int mt = 0; mt < 2; ++mt) {
                        const uint4 av = *(const uint4*)(sW + ((ks*8 + wr*2 + mt)*32 + lane)*4);
                        a[mt][0] = av.x; a[mt][1] = av.y; a[mt][2] = av.z; a[mt][3] = av.w;
                    }
                    #pragma unroll
                    for (int n = 0; n < 5; ++n) {
                        uint32_t bf[2];
                        bf[0] = xrow[n*8];
                        bf[1] = xrow[n*8 + 4*XBW];
                        MMA16(acc[0][n], a[0], bf);
                        MMA16(acc[1][n], a[1], bf);
                    }
                }
            }
            __syncthreads();   // all warps done reading sW + xbf

            if (l < 3) {       // prefetch next layer's W (overlaps epilogue)
                const uint32_t* Wg = g_Wh + (size_t)(b*N_LAYERS + l + 1)*WFULL;
                #pragma unroll
                for (int i = tid; i < WFULL/4; i += 512)
                    cp16(dW + i*16, Wg + i*4);
                CP_COMMIT();
            }

            // ---- epilogue: residual in regs; repack xbf or final out ----
            if (l < 3) {
                #pragma unroll
                for (int mt = 0; mt < 2; ++mt) {
                    #pragma unroll
                    for (int n = 0; n < 5; ++n) {
                        const int c0 = wc*40 + n*8 + (lane & 3)*2;
                        #pragma unroll
                        for (int h = 0; h < 2; ++h) {
                            const int cog = wr*32 + mt*16 + (lane >> 2) + h*8;
                            const float y0 = acc[mt][n][h*2+0] + bias_l[mt][h] + res[mt][n][h*2+0];
                            const float y1 = acc[mt][n][h*2+1] + bias_l[mt][h] + res[mt][n][h*2+1];
                            res[mt][n][h*2+0] = y0;
                            res[mt][n][h*2+1] = y1;
                            const float o0 = __shfl_xor_sync(0xffffffffu, y0, 4);
                            const float o1 = __shfl_xor_sync(0xffffffffu, y1, 4);
                            if ((lane & 4) == 0) {
                                uint2 w;
                                w.x = pack_bf16x2(y0, o0);
                                w.y = pack_bf16x2(y1, o1);
                                *(uint2*)&xbf[(cog >> 1)*XBW + 8 + c0] = w;
                            }
                        }
                    }
                }
            } else {
                float al[2][2];
                #pragma unroll
                for (int mt = 0; mt < 2; ++mt)
                    #pragma unroll
                    for (int h = 0; h < 2; ++h)
                        al[mt][h] = alpha[wr*32 + mt*16 + (lane >> 2) + h*8];
                #pragma unroll
                for (int mt = 0; mt < 2; ++mt) {
                    #pragma unroll
                    for (int n = 0; n < 5; ++n) {
                        const int c0 = wc*40 + n*8 + (lane & 3)*2;
                        if (c0 >= 16 && c0 < 144) {
                            #pragma unroll
                            for (int h = 0; h < 2; ++h) {
                                const int cog = wr*32 + mt*16 + (lane >> 2) + h*8;
                                const float y0 = acc[mt][n][h*2+0] + bias_l[mt][h] + res[mt][n][h*2+0];
                                const float y1 = acc[mt][n][h*2+1] + bias_l[mt][h] + res[mt][n][h*2+1];
                                const float a = al[mt][h];
                                const float inva = 1.0f/(a + 1e-8f);
                                const float s0 = sinf(a*y0), s1 = sinf(a*y1);
                                float2 v;
                                v.x = y0 + inva*s0*s0;
                                v.y = y1 + inva*s1*s1;
                                *(float2*)&ob[(size_t)cog*T_AUDIO + t0 + (c0 - 16)] = v;
                            }
                        }
                    }
                }
            }
            if (l < 3) CP_WAIT0();
            __syncthreads();
        }
    }
}

// =========================================================================
extern "C" void kernel_launch(void* const* d_in, const int* in_sizes, int n_in,
                              void* d_out, int out_size) {
    const float* x     = (const float*)d_in[0];
    const float* cond  = (const float*)d_in[1];
    const float* w0    = (const float*)d_in[2];
    const float* b0    = (const float*)d_in[3];
    const float* w1    = (const float*)d_in[4];
    const float* b1    = (const float*)d_in[5];
    const float* w2    = (const float*)d_in[6];
    const float* b2    = (const float*)d_in[7];
    const float* alpha = (const float*)d_in[8];
    float* out = (float*)d_out;

    const int smemA = (COND_CH*T_MEL + SW0T_N + SW1T_N + 64*T_MEL + 64*T_MEL)
                      * (int)sizeof(float);
    cudaFuncSetAttribute(condnet_kernel, cudaFuncAttributeMaxDynamicSharedMemorySize, smemA);
    condnet_kernel<<<BATCH, 1024, smemA>>>(cond, w0, b0, w1, b1);

    weights_kernel<<<386, 256>>>(w2, b2);

    cudaFuncSetAttribute(lvc_fused, cudaFuncAttributeMaxDynamicSharedMemorySize, SMEM_FUSED);
    lvc_fused<<<NCTAS, 512, SMEM_FUSED>>>(x, out, alpha);
}

// round 13
// speedup vs baseline: 1.7398x; 1.0296x over previous
#include <cuda_runtime.h>
#include <math.h>
#include <stdint.h>

#define BATCH    8
#define CH       128
#define T_AUDIO  16384
#define COND_CH  80
#define T_MEL    32
#define N_LAYERS 4
#define KPL      (CH*CH*3)        /* 49152 */
#define KC       (KPL*N_LAYERS)   /* 196608 */
#define BC       (CH*N_LAYERS)    /* 512 */

#define NT       128              /* output chunk */
#define TILES    (T_AUDIO/NT)     /* 128 */
#define NCTAS    148              /* flattened persistent grid */
#define WFULL    24576            /* per (b,l): 192 frag-rows x 32 lanes x 4 words */
#define BUFW     160              /* compute grid width (chunk + 2*16 halo) */
#define YSTR     168              /* yf32 stride: 168%32==8 -> conflict-free 64b phases */
#define XBW      184              /* xbf stride: 184%32==24 -> B frags conflict-free */

// ---------------- device scratch ----------------
__device__ float    g_h0[BATCH*64*T_MEL];
__device__ float    g_hmean[BATCH*64];
__device__ uint32_t g_Wh[BATCH*N_LAYERS*WFULL];
__device__ float    g_bias[BATCH*N_LAYERS*CH];

__device__ __forceinline__ float gelu_exact(float x) {
    return 0.5f * x * (1.0f + erff(x * 0.7071067811865475f));
}
__device__ __forceinline__ uint32_t pack_bf16x2(float lo, float hi) {
    uint32_t u;
    asm("cvt.rn.bf16x2.f32 %0, %1, %2;" : "=r"(u) : "f"(hi), "f"(lo));
    return u;
}
__device__ __forceinline__ uint32_t smem_u32(const void* p) {
    uint32_t a;
    asm("{ .reg .u64 t; cvta.to.shared.u64 t, %1; cvt.u32.u64 %0, t; }" : "=r"(a) : "l"(p));
    return a;
}
__device__ __forceinline__ void cp16(uint32_t dst, const void* src) {
    asm volatile("cp.async.cg.shared.global [%0], [%1], 16;" :: "r"(dst), "l"(src));
}
#define CP_COMMIT() asm volatile("cp.async.commit_group;" ::: "memory")
#define CP_WAIT0()  asm volatile("cp.async.wait_group 0;" ::: "memory")

#define MMA16(d_, a_, b_) \
  asm volatile("mma.sync.aligned.m16n8k16.row.col.f32.bf16.bf16.f32 " \
    "{%0,%1,%2,%3}, {%4,%5,%6,%7}, {%8,%9}, {%0,%1,%2,%3};" \
    : "+f"((d_)[0]), "+f"((d_)[1]), "+f"((d_)[2]), "+f"((d_)[3]) \
    : "r"((a_)[0]), "r"((a_)[1]), "r"((a_)[2]), "r"((a_)[3]), \
      "r"((b_)[0]), "r"((b_)[1]))

// =========================================================================
// Condnet C1: layer 0 (conv5, pad2, gelu). Grid (8 g, 8 b), 256 threads.
// Warp = one output channel; weights staged LINEAR (coalesced), read as
// warp-broadcast; cond staged zero-padded (stride 36) -> no predicates.
// =========================================================================
__global__ void __launch_bounds__(256)
cond_l0_kernel(const float* __restrict__ cond,
               const float* __restrict__ w0, const float* __restrict__ b0) {
    __shared__ float scp[COND_CH*36];     // padded: col = t+2
    __shared__ float sw[8*400];           // [ch][i*5+k] linear

    const int g = blockIdx.x;
    const int b = blockIdx.y;
    const int tid = threadIdx.x;
    const int wid = tid >> 5;
    const int lane = tid & 31;

    for (int idx = tid; idx < COND_CH*36; idx += 256) {
        const int row = idx / 36;
        const int t   = (idx - row*36) - 2;
        scp[idx] = (t >= 0 && t < T_MEL) ? cond[(b*COND_CH + row)*T_MEL + t] : 0.0f;
    }
    for (int idx = tid; idx < 8*400; idx += 256)
        sw[idx] = w0[g*8*400 + idx];
    __syncthreads();

    const float* wr = sw + wid*400;
    float acc = b0[g*8 + wid];
    #pragma unroll 4
    for (int i = 0; i < COND_CH; ++i) {
        const float4 w4 = *(const float4*)&wr[i*5];
        const float  w5 = wr[i*5 + 4];
        const float* xr = scp + i*36 + lane;
        acc += w4.x*xr[0] + w4.y*xr[1] + w4.z*xr[2] + w4.w*xr[3] + w5*xr[4];
    }
    g_h0[(b*64 + g*8 + wid)*T_MEL + lane] = gelu_exact(acc);
}

// =========================================================================
// Condnet C2: layer 1 (conv3, pad1, gelu) + mean over t. Grid 8, 1024 thr.
// Warp = 2 channels; mean via shfl_xor reduce.
// =========================================================================
__global__ void __launch_bounds__(1024)
cond_l1_kernel(const float* __restrict__ w1, const float* __restrict__ b1) {
    extern __shared__ float smemf[];
    float* shp = smemf;             // [64][34] padded: col = t+1
    float* sw1 = smemf + 64*34;     // [64][192] linear

    const int b = blockIdx.x;
    const int tid = threadIdx.x;
    const int wid = tid >> 5;
    const int lane = tid & 31;

    for (int idx = tid; idx < 64*34; idx += 1024) {
        const int row = idx / 34;
        const int t   = (idx - row*34) - 1;
        shp[idx] = (t >= 0 && t < T_MEL) ? g_h0[(b*64 + row)*T_MEL + t] : 0.0f;
    }
    for (int idx = tid; idx < 64*192; idx += 1024)
        sw1[idx] = w1[idx];
    __syncthreads();

    const int o0 = wid*2, o1 = wid*2 + 1;
    const float* wr0 = sw1 + o0*192;
    const float* wr1 = sw1 + o1*192;
    float a0 = b1[o0], a1 = b1[o1];
    #pragma unroll 4
    for (int i = 0; i < 64; ++i) {
        const float* xr = shp + i*34 + lane;
        const float x0 = xr[0], x1 = xr[1], x2 = xr[2];
        const float2 wa = *(const float2*)&wr0[i*3];
        const float  wb = wr0[i*3 + 2];
        const float2 wc = *(const float2*)&wr1[i*3];
        const float  wd = wr1[i*3 + 2];
        a0 += wa.x*x0 + wa.y*x1 + wb*x2;
        a1 += wc.x*x0 + wc.y*x1 + wd*x2;
    }
    float v0 = gelu_exact(a0);
    float v1 = gelu_exact(a1);
    #pragma unroll
    for (int off = 16; off; off >>= 1) {
        v0 += __shfl_xor_sync(0xffffffffu, v0, off);
        v1 += __shfl_xor_sync(0xffffffffu, v1, off);
    }
    if (lane == 0) {
        g_hmean[b*64 + o0] = v0 * (1.0f/T_MEL);
        g_hmean[b*64 + o1] = v1 * (1.0f/T_MEL);
    }
}

// =========================================================================
// Kernel B: LVC weights -> bf16x2 fragment-major (unchanged)
// =========================================================================
__global__ void weights_kernel(const float* __restrict__ w2,
                               const float* __restrict__ b2) {
    __shared__ float sh[BATCH*64];
    const int tid = threadIdx.x;
    for (int i = tid; i < BATCH*64; i += 256) sh[i] = g_hmean[i];
    __syncthreads();

    if (blockIdx.x < 384) {
        const int gidx = blockIdx.x*256 + tid;     // < 98304
        const int l    = gidx / WFULL;
        const int e3   = gidx - l*WFULL;
        const int j    = e3 & 3;
        const int lane = (e3 >> 2) & 31;
        const int cb   = (e3 >> 7) & 7;
        const int ks   = e3 >> 10;
        const int co   = cb*16 + (lane >> 2) + (j & 1)*8;
        const int kl0  = (lane & 3)*2 + ((j >> 1) & 1)*8;
        const int kg0  = ks*16 + kl0;
        const int kk   = kg0 >> 7;
        const int ci0  = kg0 & 127;
        const size_t r0 = (size_t)l*KPL + (size_t)co*384 + ci0*3 + kk;
        const size_t r1 = r0 + 3;

        float a0[BATCH], a1[BATCH];
        #pragma unroll
        for (int b = 0; b < BATCH; ++b) { a0[b] = 0.0f; a1[b] = 0.0f; }
        const float4* wr0 = (const float4*)(w2 + r0*64);
        const float4* wr1 = (const float4*)(w2 + r1*64);
        #pragma unroll 4
        for (int q = 0; q < 16; ++q) {
            float4 u = wr0[q], v = wr1[q];
            #pragma unroll
            for (int b = 0; b < BATCH; ++b) {
                const float* h = sh + b*64 + q*4;
                a0[b] += u.x*h[0] + u.y*h[1] + u.z*h[2] + u.w*h[3];
                a1[b] += v.x*h[0] + v.y*h[1] + v.z*h[2] + v.w*h[3];
            }
        }
        const float bi0 = b2[r0], bi1 = b2[r1];
        #pragma unroll
        for (int b = 0; b < BATCH; ++b)
            g_Wh[(size_t)(b*N_LAYERS + l)*WFULL + e3] =
                pack_bf16x2(a0[b] + bi0, a1[b] + bi1);
    } else {
        const int idx = (blockIdx.x - 384)*256 + tid;   // < 512
        const size_t c = (size_t)KC + idx;
        float acc[BATCH];
        #pragma unroll
        for (int b = 0; b < BATCH; ++b) acc[b] = 0.0f;
        const float4* wr = (const float4*)(w2 + c*64);
        #pragma unroll 4
        for (int q = 0; q < 16; ++q) {
            float4 w = wr[q];
            #pragma unroll
            for (int b = 0; b < BATCH; ++b) {
                const float* h = sh + b*64 + q*4;
                acc[b] += w.x*h[0] + w.y*h[1] + w.z*h[2] + w.w*h[3];
            }
        }
        const float bias = b2[c];
        #pragma unroll
        for (int b = 0; b < BATCH; ++b)
            g_bias[b*N_LAYERS*CH + idx] = acc[b] + bias;
    }
}

// =========================================================================
// FUSED 4-layer LVC conv, residual in registers (unchanged from R12)
// =========================================================================
#define SMEM_FUSED ((WFULL + CH*YSTR + 64*XBW) * 4)   /* 231424 B */

__global__ void __launch_bounds__(512, 1)
lvc_fused(const float* __restrict__ x, float* __restrict__ out,
          const float* __restrict__ alpha) {
    extern __shared__ __align__(16) uint32_t smem[];
    uint32_t* sW   = smem;                          // WFULL
    float*    yf32 = (float*)(smem + WFULL);        // 128 x YSTR (staging only)
    uint32_t* xbf  = smem + WFULL + CH*YSTR;        // 64 x XBW

    const int tid  = threadIdx.x;
    const int wid  = tid >> 5;
    const int lane = tid & 31;
    const int wr   = wid & 3;                       // co group (32)
    const int wc   = wid >> 2;                      // t group (40)

    const uint32_t dW = smem_u32(sW);
    const uint32_t dY = smem_u32(yf32);

    for (int g = blockIdx.x; g < BATCH*TILES; g += NCTAS) {
        const int b    = g >> 7;
        const int tile = g & (TILES - 1);
        const int t0   = tile * NT;
        const float* xb = x   + (size_t)b*CH*T_AUDIO;
        float*       ob = out + (size_t)b*CH*T_AUDIO;

        // ---- stage W0 + x chunk [t0-16, t0+144) ----
        {
            const uint32_t* Wg = g_Wh + (size_t)(b*N_LAYERS + 0)*WFULL;
            #pragma unroll
            for (int i = tid; i < WFULL/4; i += 512)
                cp16(dW + i*16, Wg + i*4);
        }
        if (t0 >= 16 && t0 + 144 <= T_AUDIO) {
            #pragma unroll
            for (int idx = tid; idx < CH*40; idx += 512) {
                const int row = idx / 40;
                const int ch  = idx - row*40;
                cp16(dY + (row*YSTR + ch*4)*4,
                     xb + (size_t)row*T_AUDIO + (t0 - 16) + ch*4);
            }
            CP_COMMIT();
            CP_WAIT0();
        } else {
            CP_COMMIT();
            for (int idx = tid; idx < CH*BUFW; idx += 512) {
                const int row = idx / BUFW;
                const int tl  = idx - row*BUFW;
                const int t   = t0 - 16 + tl;
                yf32[row*YSTR + tl] = (t >= 0 && t < T_AUDIO)
                                      ? xb[(size_t)row*T_AUDIO + t] : 0.0f;
            }
            CP_WAIT0();
        }
        __syncthreads();

        // ---- initial pack (x -> bf16x2) + load residual regs ----
        #pragma unroll
        for (int i = tid; i < 64*BUFW; i += 512) {
            const int pr = i / BUFW;
            const int tl = i - pr*BUFW;
            xbf[pr*XBW + 8 + tl] = pack_bf16x2(yf32[(2*pr)*YSTR + tl],
                                               yf32[(2*pr + 1)*YSTR + tl]);
        }
        float res[2][5][4];
        #pragma unroll
        for (int mt = 0; mt < 2; ++mt) {
            #pragma unroll
            for (int n = 0; n < 5; ++n) {
                const int c0 = wc*40 + n*8 + (lane & 3)*2;
                #pragma unroll
                for (int h = 0; h < 2; ++h) {
                    const int cog = wr*32 + mt*16 + (lane >> 2) + h*8;
                    const float2 xv = *(const float2*)&yf32[cog*YSTR + c0];
                    res[mt][n][h*2+0] = xv.x;
                    res[mt][n][h*2+1] = xv.y;
                }
            }
        }
        __syncthreads();

        // ---- 4 layers ----
        #pragma unroll 1
        for (int l = 0; l < N_LAYERS; ++l) {
            const int dil = 1 << l;

            float bias_l[2][2];
            #pragma unroll
            for (int mt = 0; mt < 2; ++mt)
                #pragma unroll
                for (int h = 0; h < 2; ++h)
                    bias_l[mt][h] = g_bias[(b*N_LAYERS + l)*CH
                                           + wr*32 + mt*16 + (lane >> 2) + h*8];

            float acc[2][5][4];
            #pragma unroll
            for (int mt = 0; mt < 2; ++mt)
                #pragma unroll
                for (int n = 0; n < 5; ++n)
                    #pragma unroll
                    for (int q = 0; q < 4; ++q) acc[mt][n][q] = 0.0f;

            #pragma unroll 1
            for (int kk = 0; kk < 3; ++kk) {
                const int off = 8 + (kk - 1)*dil;
                #pragma unroll
                for (int ks8 = 0; ks8 < 8; ++ks8) {
                    const int ks   = kk*8 + ks8;
                    const int row0 = ks8*8 + (lane & 3);
                    const uint32_t* xrow = xbf + row0*XBW + wc*40 + (lane >> 2) + off;
                    uint32_t a[2][4];
                    #pragma unroll
                    for (int mt = 0; mt < 2; ++mt) {
                        const uint4 av = *(const uint4*)(sW + ((ks*8 + wr*2 + mt)*32 + lane)*4);
                        a[mt][0] = av.x; a[mt][1] = av.y; a[mt][2] = av.z; a[mt][3] = av.w;
                    }
                    #pragma unroll
                    for (int n = 0; n < 5; ++n) {
                        uint32_t bf[2];
                        bf[0] = xrow[n*8];
                        bf[1] = xrow[n*8 + 4*XBW];
                        MMA16(acc[0][n], a[0], bf);
                        MMA16(acc[1][n], a[1], bf);
                    }
                }
            }
            __syncthreads();   // all warps done reading sW + xbf

            if (l < 3) {       // prefetch next layer's W (overlaps epilogue)
                const uint32_t* Wg = g_Wh + (size_t)(b*N_LAYERS + l + 1)*WFULL;
                #pragma unroll
                for (int i = tid; i < WFULL/4; i += 512)
                    cp16(dW + i*16, Wg + i*4);
                CP_COMMIT();
            }

            // ---- epilogue: residual in regs; repack xbf or final out ----
            if (l < 3) {
                #pragma unroll
                for (int mt = 0; mt < 2; ++mt) {
                    #pragma unroll
                    for (int n = 0; n < 5; ++n) {
                        const int c0 = wc*40 + n*8 + (lane & 3)*2;
                        #pragma unroll
                        for (int h = 0; h < 2; ++h) {
                            const int cog = wr*32 + mt*16 + (lane >> 2) + h*8;
                            const float y0 = acc[mt][n][h*2+0] + bias_l[mt][h] + res[mt][n][h*2+0];
                            const float y1 = acc[mt][n][h*2+1] + bias_l[mt][h] + res[mt][n][h*2+1];
                            res[mt][n][h*2+0] = y0;
                            res[mt][n][h*2+1] = y1;
                            const float o0 = __shfl_xor_sync(0xffffffffu, y0, 4);
                            const float o1 = __shfl_xor_sync(0xffffffffu, y1, 4);
                            if ((lane & 4) == 0) {
                                uint2 w;
                                w.x = pack_bf16x2(y0, o0);
                                w.y = pack_bf16x2(y1, o1);
                                *(uint2*)&xbf[(cog >> 1)*XBW + 8 + c0] = w;
                            }
                        }
                    }
                }
            } else {
                float al[2][2];
                #pragma unroll
                for (int mt = 0; mt < 2; ++mt)
                    #pragma unroll
                    for (int h = 0; h < 2; ++h)
                        al[mt][h] = alpha[wr*32 + mt*16 + (lane >> 2) + h*8];
                #pragma unroll
                for (int mt = 0; mt < 2; ++mt) {
                    #pragma unroll
                    for (int n = 0; n < 5; ++n) {
                        const int c0 = wc*40 + n*8 + (lane & 3)*2;
                        if (c0 >= 16 && c0 < 144) {
                            #pragma unroll
                            for (int h = 0; h < 2; ++h) {
                                const int cog = wr*32 + mt*16 + (lane >> 2) + h*8;
                                const float y0 = acc[mt][n][h*2+0] + bias_l[mt][h] + res[mt][n][h*2+0];
                                const float y1 = acc[mt][n][h*2+1] + bias_l[mt][h] + res[mt][n][h*2+1];
                                const float a = al[mt][h];
                                const float inva = 1.0f/(a + 1e-8f);
                                const float s0 = sinf(a*y0), s1 = sinf(a*y1);
                                float2 v;
                                v.x = y0 + inva*s0*s0;
                                v.y = y1 + inva*s1*s1;
                                *(float2*)&ob[(size_t)cog*T_AUDIO + t0 + (c0 - 16)] = v;
                            }
                        }
                    }
                }
            }
            if (l < 3) CP_WAIT0();
            __syncthreads();
        }
    }
}

// =========================================================================
extern "C" void kernel_launch(void* const* d_in, const int* in_sizes, int n_in,
                              void* d_out, int out_size) {
    const float* x     = (const float*)d_in[0];
    const float* cond  = (const float*)d_in[1];
    const float* w0    = (const float*)d_in[2];
    const float* b0    = (const float*)d_in[3];
    const float* w1    = (const float*)d_in[4];
    const float* b1    = (const float*)d_in[5];
    const float* w2    = (const float*)d_in[6];
    const float* b2    = (const float*)d_in[7];
    const float* alpha = (const float*)d_in[8];
    float* out = (float*)d_out;

    cond_l0_kernel<<<dim3(8, BATCH), 256>>>(cond, w0, b0);

    const int smemC2 = (64*34 + 64*192) * (int)sizeof(float);
    cudaFuncSetAttribute(cond_l1_kernel, cudaFuncAttributeMaxDynamicSharedMemorySize, smemC2);
    cond_l1_kernel<<<BATCH, 1024, smemC2>>>(w1, b1);

    weights_kernel<<<386, 256>>>(w2, b2);

    cudaFuncSetAttribute(lvc_fused, cudaFuncAttributeMaxDynamicSharedMemorySize, SMEM_FUSED);
    lvc_fused<<<NCTAS, 512, SMEM_FUSED>>>(x, out, alpha);
}